// round 9
// baseline (speedup 1.0000x reference)
#include <cuda_runtime.h>
#include <cstdint>

#define NN      100000
#define DIM     256
#define NRELS   8
#define EPR     160000

#define TM 128
#define KB 32
#define APAD 4
#define BPAD 8
#define NSTAGE 3
#define NTHREADS 512

#define A_STRIDE (KB + APAD)      // 36 floats
#define B_STRIDE (DIM + BPAD)     // 264 floats
#define SMEM_BYTES ((NSTAGE * KB * B_STRIDE + NSTAGE * TM * A_STRIDE) * 4 + 2 * TM * 4)

// Scratch for normalized int32 indices (metadata may be int32 or int64 — detected at runtime)
__device__ int g_src32[NRELS * EPR];
__device__ int g_dst32[NRELS * EPR];
__device__ int g_idx_is_i32;

__device__ __forceinline__ void mma_tf32(float c[4], const unsigned a[4], const unsigned b[2]) {
    asm volatile(
        "mma.sync.aligned.m16n8k8.row.col.f32.tf32.tf32.f32 "
        "{%0,%1,%2,%3}, {%4,%5,%6,%7}, {%8,%9}, {%0,%1,%2,%3};\n"
        : "+f"(c[0]), "+f"(c[1]), "+f"(c[2]), "+f"(c[3])
        : "r"(a[0]), "r"(a[1]), "r"(a[2]), "r"(a[3]), "r"(b[0]), "r"(b[1]));
}

__device__ __forceinline__ void red_v4(float* addr, float v0, float v1, float v2, float v3) {
    asm volatile("red.global.add.v4.f32 [%0], {%1, %2, %3, %4};"
                 :: "l"(addr), "f"(v0), "f"(v1), "f"(v2), "f"(v3) : "memory");
}

__device__ __forceinline__ void cp_async16(uint32_t smem_addr, const void* gptr) {
    asm volatile("cp.async.cg.shared.global [%0], [%1], 16;"
                 :: "r"(smem_addr), "l"(gptr) : "memory");
}
__device__ __forceinline__ void cp_commit() {
    asm volatile("cp.async.commit_group;" ::: "memory");
}
__device__ __forceinline__ void cp_wait1() {
    asm volatile("cp.async.wait_group 1;" ::: "memory");
}

// ---------------------------------------------------------------------------
// Index dtype detection
// ---------------------------------------------------------------------------
__global__ void detect_idx_kernel(const void* srcbuf) {
    const long long* p = (const long long*)srcbuf;
    int tid = threadIdx.x;
    int bad = 0;
    #pragma unroll
    for (int i = 0; i < 4; i++) {
        long long v = p[tid * 4 + i];
        if (v < 0 || v >= NN) bad = 1;
    }
    int any = __syncthreads_or(bad);
    if (tid == 0) g_idx_is_i32 = any;   // any out-of-range -> data is int32
}

__global__ void convert_idx_kernel(const void* srcbuf, const void* dstbuf) {
    long long i = (long long)blockIdx.x * blockDim.x + threadIdx.x;
    if (i >= (long long)NRELS * EPR) return;
    if (g_idx_is_i32) {
        g_src32[i] = ((const int*)srcbuf)[i];
        g_dst32[i] = ((const int*)dstbuf)[i];
    } else {
        g_src32[i] = (int)((const long long*)srcbuf)[i];
        g_dst32[i] = (int)((const long long*)dstbuf)[i];
    }
}

// ---------------------------------------------------------------------------
// 3-stage cp.async pipelined tf32 GEMM, single barrier per K-chunk.
// Raw fp32 fed directly to tf32 MMA (low-mantissa truncation; LayerNorm's
// scale invariance cancels the systematic shrink).
// Block: 512 threads = 16 warps (4x4), tile M=128 x N=256, K chunks of 32.
// GATHER=false: C[m,:] = X[m,:] @ W, direct store (self loop).
// GATHER=true:  per relation, C[e,:] = X[src[e],:] @ W_rel, red.v4 scatter.
// ---------------------------------------------------------------------------
template<bool GATHER, bool ATOMIC>
__global__ __launch_bounds__(NTHREADS, 1) void rgcn_gemm_kernel(const float* __restrict__ X,
                                                                const float* __restrict__ W,
                                                                float* __restrict__ out)
{
    extern __shared__ float dyn[];
    float* BsBase = dyn;                                    // [NSTAGE][KB][B_STRIDE]
    float* AsBase = dyn + NSTAGE * KB * B_STRIDE;           // [NSTAGE][TM][A_STRIDE]
    int*   sSrc   = (int*)(AsBase + NSTAGE * TM * A_STRIDE);
    int*   sDst   = sSrc + TM;

    const int tid = threadIdx.x;
    const int rel = GATHER ? blockIdx.y : 0;
    const long long base = (long long)blockIdx.x * TM;

    const float* Wr = GATHER ? (W + (size_t)rel * DIM * DIM) : W;

    if (tid < TM) {
        if constexpr (GATHER) {
            long long off = (long long)rel * EPR + base + tid;
            sSrc[tid] = g_src32[off];
            sDst[tid] = g_dst32[off];
        } else {
            long long r = base + tid;
            sSrc[tid] = (r < NN) ? (int)r : 0;
            sDst[tid] = (r < NN) ? (int)r : -1;
        }
    }
    __syncthreads();

    const int warp = tid >> 5;
    const int lane = tid & 31;
    const int wm = warp >> 2;     // 0..3
    const int wn = warp & 3;      // 0..3
    const int g  = lane >> 2;     // 0..7
    const int t4 = lane & 3;      // 0..3

    // Staging assignment (512 threads):
    // A chunk: 128 rows x 32 floats = 1024 float4 -> 2 cp.async16/thread
    // B chunk: 32 rows x 256 floats = 2048 float4 -> 4 cp.async16/thread
    const int arow  = tid >> 2;          // 0..127
    const int acol  = (tid & 3) << 3;    // 0,8,16,24
    const int brow0 = tid >> 6;          // 0..7
    const int bcol  = (tid & 63) << 2;   // 0..252

    const float* aPtr = X + (size_t)sSrc[arow] * DIM + acol;
    const float* bPtr = Wr + (size_t)brow0 * DIM + bcol;

    const uint32_t sA = (uint32_t)__cvta_generic_to_shared(
        AsBase + (size_t)arow * A_STRIDE + acol);
    const uint32_t sB = (uint32_t)__cvta_generic_to_shared(
        BsBase + (size_t)brow0 * B_STRIDE + bcol);
    const uint32_t ABUF = (uint32_t)(TM * A_STRIDE * 4);   // bytes per A stage
    const uint32_t BBUF = (uint32_t)(KB * B_STRIDE * 4);   // bytes per B stage

    auto stage = [&](int kb, int buf) {
        uint32_t aoff = (uint32_t)buf * ABUF;
        uint32_t boff = (uint32_t)buf * BBUF;
        cp_async16(sA + aoff,      aPtr + kb);
        cp_async16(sA + aoff + 16, aPtr + kb + 4);
        #pragma unroll
        for (int rr = 0; rr < 4; rr++)
            cp_async16(sB + boff + rr * 8 * B_STRIDE * 4,
                       bPtr + (size_t)(kb + rr * 8) * DIM);
    };

    float c[2][8][4];
    #pragma unroll
    for (int mi = 0; mi < 2; mi++)
        #pragma unroll
        for (int j = 0; j < 8; j++)
            #pragma unroll
            for (int q = 0; q < 4; q++)
                c[mi][j][q] = 0.f;

    // Prologue: prefetch chunks 0 and 1
    stage(0, 0); cp_commit();
    stage(KB, 1); cp_commit();

    const int NCHUNK = DIM / KB;   // 8
    #pragma unroll 1
    for (int kc = 0; kc < NCHUNK; kc++) {
        cp_wait1();          // group kc complete (allow newest 1 pending)
        __syncthreads();     // data visible to all warps; all warps done reading buf (kc+2)%3

        // Stage kc+2 into buffer (kc+2)%3 — safe: last read in compute(kc-1),
        // which every warp finished before the barrier above.
        if (kc + 2 < NCHUNK) stage((kc + 2) * KB, (kc + 2) % NSTAGE);
        cp_commit();         // uniform group accounting (empty group is legal)

        const unsigned* Ab = (const unsigned*)(AsBase + (size_t)(kc % NSTAGE) * TM * A_STRIDE);
        const unsigned* Bb = (const unsigned*)(BsBase + (size_t)(kc % NSTAGE) * KB * B_STRIDE);

        #pragma unroll
        for (int s = 0; s < 4; s++) {
            unsigned a[2][4], b[8][2];
            #pragma unroll
            for (int mi = 0; mi < 2; mi++) {
                int rb = wm * 32 + mi * 16 + g;
                a[mi][0] = Ab[(size_t)rb        * A_STRIDE + 8 * s + t4];
                a[mi][1] = Ab[(size_t)(rb + 8)  * A_STRIDE + 8 * s + t4];
                a[mi][2] = Ab[(size_t)rb        * A_STRIDE + 8 * s + t4 + 4];
                a[mi][3] = Ab[(size_t)(rb + 8)  * A_STRIDE + 8 * s + t4 + 4];
            }
            #pragma unroll
            for (int j = 0; j < 8; j++) {
                int n = wn * 64 + j * 8 + g;
                b[j][0] = Bb[(size_t)(8 * s + t4)     * B_STRIDE + n];
                b[j][1] = Bb[(size_t)(8 * s + t4 + 4) * B_STRIDE + n];
            }
            #pragma unroll
            for (int mi = 0; mi < 2; mi++)
                #pragma unroll
                for (int j = 0; j < 8; j++)
                    mma_tf32(c[mi][j], a[mi], b[j]);
        }
        // no trailing barrier: next iteration's barrier provides WAR protection
    }

    // ---- epilogue ----
    if constexpr (ATOMIC) {
        const bool odd = (lane & 1);
        const int colbase = wn * 64 + ((t4 & ~1) << 1);   // 16B-aligned column
        #pragma unroll
        for (int mi = 0; mi < 2; mi++) {
            int rowsel = wm * 32 + mi * 16 + (odd ? 8 : 0) + g;
            int drow = sDst[rowsel];
            float* addr = out + (size_t)drow * DIM + colbase;
            #pragma unroll
            for (int j = 0; j < 8; j++) {
                float s0 = __shfl_xor_sync(0xffffffffu, odd ? c[mi][j][0] : c[mi][j][2], 1);
                float s1 = __shfl_xor_sync(0xffffffffu, odd ? c[mi][j][1] : c[mi][j][3], 1);
                float v0, v1, v2, v3;
                if (!odd) { v0 = c[mi][j][0]; v1 = c[mi][j][1]; v2 = s0; v3 = s1; }
                else      { v0 = s0;          v1 = s1;          v2 = c[mi][j][2]; v3 = c[mi][j][3]; }
                red_v4(addr + j * 8, v0, v1, v2, v3);
            }
        }
    } else {
        #pragma unroll
        for (int mi = 0; mi < 2; mi++) {
            #pragma unroll
            for (int half = 0; half < 2; half++) {
                int r = wm * 32 + mi * 16 + half * 8 + g;
                int drow = sDst[r];
                if (drow < 0) continue;
                float* orow = out + (size_t)drow * DIM + wn * 64;
                #pragma unroll
                for (int j = 0; j < 8; j++) {
                    int col = j * 8 + t4 * 2;
                    float v0 = c[mi][j][half * 2 + 0];
                    float v1 = c[mi][j][half * 2 + 1];
                    *reinterpret_cast<float2*>(orow + col) = make_float2(v0, v1);
                }
            }
        }
    }
}

// ---------------------------------------------------------------------------
// LayerNorm over last dim (256). One warp per row.
// ---------------------------------------------------------------------------
__global__ void ln_kernel(float* __restrict__ out,
                          const float* __restrict__ gamma,
                          const float* __restrict__ beta)
{
    int row = blockIdx.x * 8 + (threadIdx.x >> 5);
    if (row >= NN) return;
    int lane = threadIdx.x & 31;
    float* p = out + (size_t)row * DIM;

    float4 v0 = *reinterpret_cast<const float4*>(p + lane * 4);
    float4 v1 = *reinterpret_cast<const float4*>(p + 128 + lane * 4);

    float s  = v0.x + v0.y + v0.z + v0.w + v1.x + v1.y + v1.z + v1.w;
    float sq = fmaf(v0.x, v0.x, fmaf(v0.y, v0.y, fmaf(v0.z, v0.z, v0.w * v0.w)))
             + fmaf(v1.x, v1.x, fmaf(v1.y, v1.y, fmaf(v1.z, v1.z, v1.w * v1.w)));

    #pragma unroll
    for (int o = 16; o; o >>= 1) {
        s  += __shfl_xor_sync(0xffffffffu, s,  o);
        sq += __shfl_xor_sync(0xffffffffu, sq, o);
    }

    float mean = s * (1.f / 256.f);
    float var  = sq * (1.f / 256.f) - mean * mean;
    float rs   = rsqrtf(var + 1e-5f);

    float4 g0 = *reinterpret_cast<const float4*>(gamma + lane * 4);
    float4 g1 = *reinterpret_cast<const float4*>(gamma + 128 + lane * 4);
    float4 b0 = *reinterpret_cast<const float4*>(beta + lane * 4);
    float4 b1 = *reinterpret_cast<const float4*>(beta + 128 + lane * 4);

    v0.x = (v0.x - mean) * rs * g0.x + b0.x;
    v0.y = (v0.y - mean) * rs * g0.y + b0.y;
    v0.z = (v0.z - mean) * rs * g0.z + b0.z;
    v0.w = (v0.w - mean) * rs * g0.w + b0.w;
    v1.x = (v1.x - mean) * rs * g1.x + b1.x;
    v1.y = (v1.y - mean) * rs * g1.y + b1.y;
    v1.z = (v1.z - mean) * rs * g1.z + b1.z;
    v1.w = (v1.w - mean) * rs * g1.w + b1.w;

    *reinterpret_cast<float4*>(p + lane * 4)       = v0;
    *reinterpret_cast<float4*>(p + 128 + lane * 4) = v1;
}

extern "C" void kernel_launch(void* const* d_in, const int* in_sizes, int n_in,
                              void* d_out, int out_size)
{
    const float* x     = (const float*)d_in[0];
    const void*  srcb  = d_in[1];
    const void*  dstb  = d_in[2];
    const float* Wself = (const float*)d_in[3];
    const float* Wrel  = (const float*)d_in[4];
    const float* gamma = (const float*)d_in[5];
    const float* beta  = (const float*)d_in[6];
    float* out = (float*)d_out;

    // Allow >48KB dynamic smem (attribute set is idempotent & capture-safe)
    cudaFuncSetAttribute(rgcn_gemm_kernel<false, false>,
                         cudaFuncAttributeMaxDynamicSharedMemorySize, SMEM_BYTES);
    cudaFuncSetAttribute(rgcn_gemm_kernel<true, true>,
                         cudaFuncAttributeMaxDynamicSharedMemorySize, SMEM_BYTES);

    // Normalize indices to int32 scratch (handles int32 or int64 input dtype)
    detect_idx_kernel<<<1, 256>>>(srcb);
    {
        long long total = (long long)NRELS * EPR;
        int blocks = (int)((total + 255) / 256);
        convert_idx_kernel<<<blocks, 256>>>(srcb, dstb);
    }

    // 1) self loop: out = x @ W_self  (initializes all of out)
    rgcn_gemm_kernel<false, false><<<(NN + TM - 1) / TM, NTHREADS, SMEM_BYTES>>>(x, Wself, out);

    // 2) fused gather -> tf32 GEMM -> red.v4 scatter for all relations
    rgcn_gemm_kernel<true, true><<<dim3(EPR / TM, NRELS), NTHREADS, SMEM_BYTES>>>(x, Wrel, out);

    // 3) LayerNorm
    ln_kernel<<<(NN + 7) / 8, 256>>>(out, gamma, beta);
}

// round 11
// speedup vs baseline: 1.0837x; 1.0837x over previous
#include <cuda_runtime.h>
#include <cuda_fp16.h>
#include <cstdint>

#define NN      100000
#define DIM     256
#define NRELS   8
#define EPR     160000

#define TM      64           // edges per block
#define KBE     64           // K elements (halves) per chunk = 128B rows
#define NCHUNK  (DIM / KBE)  // 4

// smem layout (bytes). Row stride 144B = 72 halves (64 data + 8 pad) for both
// A (64 rows) and B (256 rows). Padded stride 36 words -> conflict-free frags.
#define ROWB    144
#define B_STAGE (DIM * ROWB)          // 36864
#define A_STAGE (TM * ROWB)           // 9216
#define OFF_B0  0
#define OFF_B1  B_STAGE
#define OFF_A0  (2 * B_STAGE)
#define OFF_A1  (2 * B_STAGE + A_STAGE)
#define OFF_SRC (2 * B_STAGE + 2 * A_STAGE)
#define OFF_DST (OFF_SRC + TM * 4)
#define SMEM_TOTAL (OFF_DST + TM * 4)   // 92672 B -> 2 CTAs/SM

// ---------------------------------------------------------------------------
// device scratch
// ---------------------------------------------------------------------------
__device__ int     g_src32[NRELS * EPR];
__device__ int     g_dst32[NRELS * EPR];
__device__ int     g_idx_is_i32;
__device__ __half2 g_xh[NN * DIM / 2];           // x converted to fp16 (51.2MB, L2-resident)
__device__ __half  g_WrelT[NRELS * DIM * DIM];   // W_rel -> [r][n][k] fp16
__device__ __half  g_WselfT[DIM * DIM];          // W_self -> [n][k] fp16

// ---------------------------------------------------------------------------
// helpers
// ---------------------------------------------------------------------------
__device__ __forceinline__ void mma_f16(float c[4], const unsigned a[4], const unsigned b[2]) {
    asm volatile(
        "mma.sync.aligned.m16n8k16.row.col.f32.f16.f16.f32 "
        "{%0,%1,%2,%3}, {%4,%5,%6,%7}, {%8,%9}, {%0,%1,%2,%3};\n"
        : "+f"(c[0]), "+f"(c[1]), "+f"(c[2]), "+f"(c[3])
        : "r"(a[0]), "r"(a[1]), "r"(a[2]), "r"(a[3]), "r"(b[0]), "r"(b[1]));
}

__device__ __forceinline__ void red_v4(float* addr, float v0, float v1, float v2, float v3) {
    asm volatile("red.global.add.v4.f32 [%0], {%1, %2, %3, %4};"
                 :: "l"(addr), "f"(v0), "f"(v1), "f"(v2), "f"(v3) : "memory");
}

__device__ __forceinline__ void cp_async16(uint32_t saddr, const void* g) {
    asm volatile("cp.async.cg.shared.global [%0], [%1], 16;" :: "r"(saddr), "l"(g) : "memory");
}
__device__ __forceinline__ void cp_commit() { asm volatile("cp.async.commit_group;" ::: "memory"); }
__device__ __forceinline__ void cp_wait1()  { asm volatile("cp.async.wait_group 1;" ::: "memory"); }

// ---------------------------------------------------------------------------
// Index dtype detection + normalization (int32 or int64 input)
// ---------------------------------------------------------------------------
__global__ void detect_idx_kernel(const void* srcbuf) {
    const long long* p = (const long long*)srcbuf;
    int tid = threadIdx.x;
    int bad = 0;
    #pragma unroll
    for (int i = 0; i < 4; i++) {
        long long v = p[tid * 4 + i];
        if (v < 0 || v >= NN) bad = 1;
    }
    int any = __syncthreads_or(bad);
    if (tid == 0) g_idx_is_i32 = any;
}

__global__ void convert_idx_kernel(const void* srcbuf, const void* dstbuf) {
    long long i = (long long)blockIdx.x * blockDim.x + threadIdx.x;
    if (i >= (long long)NRELS * EPR) return;
    if (g_idx_is_i32) {
        g_src32[i] = ((const int*)srcbuf)[i];
        g_dst32[i] = ((const int*)dstbuf)[i];
    } else {
        g_src32[i] = (int)((const long long*)srcbuf)[i];
        g_dst32[i] = (int)((const long long*)dstbuf)[i];
    }
}

// ---------------------------------------------------------------------------
// x -> fp16 (half2 packed), 12.8M half2 elements
// ---------------------------------------------------------------------------
__global__ void x_to_half(const float* __restrict__ x) {
    long long i = (long long)blockIdx.x * blockDim.x + threadIdx.x;
    if (i >= (long long)NN * DIM / 2) return;
    float2 v = ((const float2*)x)[i];
    g_xh[i] = __floats2half2_rn(v.x, v.y);
}

// ---------------------------------------------------------------------------
// W [k][n] -> fp16 [n][k], per 256x256 matrix (blockIdx.z = matrix id)
// ---------------------------------------------------------------------------
__global__ void wt_half(const float* __restrict__ src, __half* __restrict__ dst) {
    __shared__ float t[32][33];
    const float* S = src + (size_t)blockIdx.z * DIM * DIM;
    __half* D = dst + (size_t)blockIdx.z * DIM * DIM;
    int bx = blockIdx.x * 32, by = blockIdx.y * 32;
    t[threadIdx.y][threadIdx.x] = S[(size_t)(by + threadIdx.y) * DIM + bx + threadIdx.x];
    __syncthreads();
    D[(size_t)(bx + threadIdx.y) * DIM + by + threadIdx.x] =
        __float2half_rn(t[threadIdx.x][threadIdx.y]);
}

// ---------------------------------------------------------------------------
// fp16 double-buffered cp.async GEMM, fp32 accumulate.
// Block: 256 threads = 8 warps (2x4), tile M=64 x N=256, 4 K-chunks of 64.
// A[m][k] fp16 rows (gathered x), B[n][k] fp16 rows (pre-transposed W).
// GATHER=false: direct store (self loop). GATHER=true: red.v4 scatter.
// ---------------------------------------------------------------------------
template<bool GATHER>
__global__ __launch_bounds__(256, 2)
void rgcn_gemm_f16(const __half* __restrict__ XH,
                   const __half* __restrict__ WT,
                   float* __restrict__ out)
{
    extern __shared__ char smem[];
    int* sSrc = (int*)(smem + OFF_SRC);
    int* sDst = (int*)(smem + OFF_DST);

    const int tid = threadIdx.x;
    const int rel = GATHER ? blockIdx.y : 0;
    const long long base = (long long)blockIdx.x * TM;
    const __half* Wr = WT + (size_t)rel * DIM * DIM;

    if (tid < TM) {
        if constexpr (GATHER) {
            long long off = (long long)rel * EPR + base + tid;
            sSrc[tid] = g_src32[off];
            sDst[tid] = g_dst32[off];
        } else {
            long long r = base + tid;
            sSrc[tid] = (r < NN) ? (int)r : 0;
            sDst[tid] = (r < NN) ? (int)r : -1;
        }
    }
    __syncthreads();

    const int warp = tid >> 5;
    const int lane = tid & 31;
    const int wm = warp >> 2;     // 0..1
    const int wn = warp & 3;      // 0..3
    const int g  = lane >> 2;     // 0..7
    const int t4 = lane & 3;      // 0..3

    // Staging: A chunk = 64 rows x 128B (8 granules/row); thread t -> row t/4,
    // granules (t&3) and (t&3)+4. B chunk = 256 rows x 128B; thread t -> row t,
    // granules 0..7.
    const int arow = tid >> 2;
    const int ac   = tid & 3;
    const char* aSrc = (const char*)(XH + (size_t)sSrc[arow] * DIM);
    const char* bSrc = (const char*)(Wr + (size_t)tid * DIM);

    uint32_t sb;
    asm("{ .reg .u64 t; cvta.to.shared.u64 t, %1; cvt.u32.u64 %0, t; }" : "=r"(sb) : "l"(smem));

    const uint32_t offA[2] = { sb + OFF_A0, sb + OFF_A1 };
    const uint32_t offB[2] = { sb + OFF_B0, sb + OFF_B1 };

    auto stage = [&](int kc, int buf) {
        // A: 2 granules
        cp_async16(offA[buf] + arow * ROWB + ac * 16,       aSrc + kc * 128 + ac * 16);
        cp_async16(offA[buf] + arow * ROWB + (ac + 4) * 16, aSrc + kc * 128 + (ac + 4) * 16);
        // B: 8 granules
        #pragma unroll
        for (int i = 0; i < 8; i++)
            cp_async16(offB[buf] + tid * ROWB + i * 16, bSrc + kc * 128 + i * 16);
    };

    float c[2][8][4];
    #pragma unroll
    for (int mi = 0; mi < 2; mi++)
        #pragma unroll
        for (int j = 0; j < 8; j++)
            #pragma unroll
            for (int q = 0; q < 4; q++)
                c[mi][j][q] = 0.f;

    stage(0, 0);
    cp_commit();

    #pragma unroll 1
    for (int kc = 0; kc < NCHUNK; kc++) {
        if (kc + 1 < NCHUNK) stage(kc + 1, (kc + 1) & 1);
        cp_commit();
        cp_wait1();
        __syncthreads();

        // half2-word views, row stride 36 words (72 halves)
        const unsigned* Ab = (const unsigned*)(smem + ((kc & 1) ? OFF_A1 : OFF_A0));
        const unsigned* Bb = (const unsigned*)(smem + ((kc & 1) ? OFF_B1 : OFF_B0));

        #pragma unroll
        for (int s = 0; s < 4; s++) {       // 4 x k16 steps per 64-chunk
            unsigned a[2][4], b[8][2];
            #pragma unroll
            for (int mi = 0; mi < 2; mi++) {
                int rb = wm * 32 + mi * 16 + g;
                a[mi][0] = Ab[(size_t)rb       * 36 + s * 8 + t4];
                a[mi][1] = Ab[(size_t)(rb + 8) * 36 + s * 8 + t4];
                a[mi][2] = Ab[(size_t)rb       * 36 + s * 8 + t4 + 4];
                a[mi][3] = Ab[(size_t)(rb + 8) * 36 + s * 8 + t4 + 4];
            }
            #pragma unroll
            for (int j = 0; j < 8; j++) {
                int n = wn * 64 + j * 8 + g;
                b[j][0] = Bb[(size_t)n * 36 + s * 8 + t4];
                b[j][1] = Bb[(size_t)n * 36 + s * 8 + t4 + 4];
            }
            #pragma unroll
            for (int mi = 0; mi < 2; mi++)
                #pragma unroll
                for (int j = 0; j < 8; j++)
                    mma_f16(c[mi][j], a[mi], b[j]);
        }
        __syncthreads();
    }

    // ---- epilogue (identical accumulator layout to m16n8k8) ----
    if constexpr (GATHER) {
        const bool odd = (lane & 1);
        const int colbase = wn * 64 + ((t4 & ~1) << 1);
        #pragma unroll
        for (int mi = 0; mi < 2; mi++) {
            int rowsel = wm * 32 + mi * 16 + (odd ? 8 : 0) + g;
            int drow = sDst[rowsel];
            float* addr = out + (size_t)drow * DIM + colbase;
            #pragma unroll
            for (int j = 0; j < 8; j++) {
                float s0 = __shfl_xor_sync(0xffffffffu, odd ? c[mi][j][0] : c[mi][j][2], 1);
                float s1 = __shfl_xor_sync(0xffffffffu, odd ? c[mi][j][1] : c[mi][j][3], 1);
                float v0, v1, v2, v3;
                if (!odd) { v0 = c[mi][j][0]; v1 = c[mi][j][1]; v2 = s0; v3 = s1; }
                else      { v0 = s0;          v1 = s1;          v2 = c[mi][j][2]; v3 = c[mi][j][3]; }
                red_v4(addr + j * 8, v0, v1, v2, v3);
            }
        }
    } else {
        #pragma unroll
        for (int mi = 0; mi < 2; mi++) {
            #pragma unroll
            for (int half = 0; half < 2; half++) {
                int r = wm * 32 + mi * 16 + half * 8 + g;
                int drow = sDst[r];
                if (drow < 0) continue;
                float* orow = out + (size_t)drow * DIM + wn * 64;
                #pragma unroll
                for (int j = 0; j < 8; j++) {
                    int col = j * 8 + t4 * 2;
                    float v0 = c[mi][j][half * 2 + 0];
                    float v1 = c[mi][j][half * 2 + 1];
                    *reinterpret_cast<float2*>(orow + col) = make_float2(v0, v1);
                }
            }
        }
    }
}

// ---------------------------------------------------------------------------
// LayerNorm over last dim (256). One warp per row.
// ---------------------------------------------------------------------------
__global__ void ln_kernel(float* __restrict__ out,
                          const float* __restrict__ gamma,
                          const float* __restrict__ beta)
{
    int row = blockIdx.x * 8 + (threadIdx.x >> 5);
    if (row >= NN) return;
    int lane = threadIdx.x & 31;
    float* p = out + (size_t)row * DIM;

    float4 v0 = *reinterpret_cast<const float4*>(p + lane * 4);
    float4 v1 = *reinterpret_cast<const float4*>(p + 128 + lane * 4);

    float s  = v0.x + v0.y + v0.z + v0.w + v1.x + v1.y + v1.z + v1.w;
    float sq = fmaf(v0.x, v0.x, fmaf(v0.y, v0.y, fmaf(v0.z, v0.z, v0.w * v0.w)))
             + fmaf(v1.x, v1.x, fmaf(v1.y, v1.y, fmaf(v1.z, v1.z, v1.w * v1.w)));

    #pragma unroll
    for (int o = 16; o; o >>= 1) {
        s  += __shfl_xor_sync(0xffffffffu, s,  o);
        sq += __shfl_xor_sync(0xffffffffu, sq, o);
    }

    float mean = s * (1.f / 256.f);
    float var  = sq * (1.f / 256.f) - mean * mean;
    float rs   = rsqrtf(var + 1e-5f);

    float4 g0 = *reinterpret_cast<const float4*>(gamma + lane * 4);
    float4 g1 = *reinterpret_cast<const float4*>(gamma + 128 + lane * 4);
    float4 b0 = *reinterpret_cast<const float4*>(beta + lane * 4);
    float4 b1 = *reinterpret_cast<const float4*>(beta + 128 + lane * 4);

    v0.x = (v0.x - mean) * rs * g0.x + b0.x;
    v0.y = (v0.y - mean) * rs * g0.y + b0.y;
    v0.z = (v0.z - mean) * rs * g0.z + b0.z;
    v0.w = (v0.w - mean) * rs * g0.w + b0.w;
    v1.x = (v1.x - mean) * rs * g1.x + b1.x;
    v1.y = (v1.y - mean) * rs * g1.y + b1.y;
    v1.z = (v1.z - mean) * rs * g1.z + b1.z;
    v1.w = (v1.w - mean) * rs * g1.w + b1.w;

    *reinterpret_cast<float4*>(p + lane * 4)       = v0;
    *reinterpret_cast<float4*>(p + 128 + lane * 4) = v1;
}

extern "C" void kernel_launch(void* const* d_in, const int* in_sizes, int n_in,
                              void* d_out, int out_size)
{
    const float* x     = (const float*)d_in[0];
    const void*  srcb  = d_in[1];
    const void*  dstb  = d_in[2];
    const float* Wself = (const float*)d_in[3];
    const float* Wrel  = (const float*)d_in[4];
    const float* gamma = (const float*)d_in[5];
    const float* beta  = (const float*)d_in[6];
    float* out = (float*)d_out;

    void *pXh = nullptr, *pWrelT = nullptr, *pWselfT = nullptr;
    cudaGetSymbolAddress(&pXh, g_xh);
    cudaGetSymbolAddress(&pWrelT, g_WrelT);
    cudaGetSymbolAddress(&pWselfT, g_WselfT);

    cudaFuncSetAttribute(rgcn_gemm_f16<false>,
                         cudaFuncAttributeMaxDynamicSharedMemorySize, SMEM_TOTAL);
    cudaFuncSetAttribute(rgcn_gemm_f16<true>,
                         cudaFuncAttributeMaxDynamicSharedMemorySize, SMEM_TOTAL);

    // Normalize indices to int32 scratch
    detect_idx_kernel<<<1, 256>>>(srcb);
    {
        long long total = (long long)NRELS * EPR;
        convert_idx_kernel<<<(int)((total + 255) / 256), 256>>>(srcb, dstb);
    }

    // Prepass: x -> fp16; W -> fp16 transposed [n][k]
    {
        long long nh2 = (long long)NN * DIM / 2;
        x_to_half<<<(int)((nh2 + 255) / 256), 256>>>(x);
        wt_half<<<dim3(8, 8, NRELS), dim3(32, 32)>>>(Wrel, (__half*)pWrelT);
        wt_half<<<dim3(8, 8, 1), dim3(32, 32)>>>(Wself, (__half*)pWselfT);
    }

    // 1) self loop: out = x @ W_self (direct store initializes out)
    rgcn_gemm_f16<false><<<(NN + TM - 1) / TM, 256, SMEM_TOTAL>>>(
        (const __half*)pXh, (const __half*)pWselfT, out);

    // 2) fused gather -> fp16 GEMM -> red.v4 scatter for all relations
    rgcn_gemm_f16<true><<<dim3(EPR / TM, NRELS), 256, SMEM_TOTAL>>>(
        (const __half*)pXh, (const __half*)pWrelT, out);

    // 3) LayerNorm
    ln_kernel<<<(NN + 7) / 8, 256>>>(out, gamma, beta);
}

// round 12
// speedup vs baseline: 1.1515x; 1.0625x over previous
#include <cuda_runtime.h>
#include <cuda_fp16.h>
#include <cstdint>

#define NN      100000
#define DIM     256
#define NRELS   8
#define EPR     160000
#define NEDGES  (NRELS * EPR)
#define NBINS   (NRELS * NN)

#define TM      64           // edges per block
#define KBE     64           // K halves per chunk = 128B rows
#define NCHUNK  (DIM / KBE)  // 4

// smem: row stride 144B = 72 halves (64 data + 8 pad)
#define ROWB    144
#define B_STAGE (DIM * ROWB)          // 36864
#define A_STAGE (TM * ROWB)           // 9216
#define OFF_B0  0
#define OFF_B1  B_STAGE
#define OFF_A0  (2 * B_STAGE)
#define OFF_A1  (2 * B_STAGE + A_STAGE)
#define OFF_SRC (2 * B_STAGE + 2 * A_STAGE)   // 92160
#define OFF_DST (OFF_SRC + TM * 4)
#define SMEM_TOTAL (OFF_DST + TM * 4)         // 92672 -> 2 CTAs/SM
#define CS_STRIDE 260                          // C-tile smem stride (floats)

#define SCAN_BLK 1024
#define NSCANBLK ((NBINS + SCAN_BLK - 1) / SCAN_BLK)   // 782

// ---------------------------------------------------------------------------
// device scratch
// ---------------------------------------------------------------------------
__device__ int     g_src32[NEDGES];            // dst-sorted per relation
__device__ int     g_dst32[NEDGES];
__device__ int     g_idx_is_i32;
__device__ int     g_off[NBINS];               // exclusive-scanned histogram
__device__ int     g_bsum[SCAN_BLK];
__device__ __half2 g_xh[NN * DIM / 2];         // x -> fp16 (51.2MB)
__device__ __half  g_WrelT[NRELS * DIM * DIM]; // W_rel -> [r][n][k] fp16
__device__ __half  g_WselfT[DIM * DIM];        // W_self -> [n][k] fp16

// ---------------------------------------------------------------------------
// helpers
// ---------------------------------------------------------------------------
__device__ __forceinline__ void mma_f16(float c[4], const unsigned a[4], const unsigned b[2]) {
    asm volatile(
        "mma.sync.aligned.m16n8k16.row.col.f32.f16.f16.f32 "
        "{%0,%1,%2,%3}, {%4,%5,%6,%7}, {%8,%9}, {%0,%1,%2,%3};\n"
        : "+f"(c[0]), "+f"(c[1]), "+f"(c[2]), "+f"(c[3])
        : "r"(a[0]), "r"(a[1]), "r"(a[2]), "r"(a[3]), "r"(b[0]), "r"(b[1]));
}

__device__ __forceinline__ void red_v4(float* addr, float v0, float v1, float v2, float v3) {
    asm volatile("red.global.add.v4.f32 [%0], {%1, %2, %3, %4};"
                 :: "l"(addr), "f"(v0), "f"(v1), "f"(v2), "f"(v3) : "memory");
}

__device__ __forceinline__ void cp_async16(uint32_t saddr, const void* g) {
    asm volatile("cp.async.cg.shared.global [%0], [%1], 16;" :: "r"(saddr), "l"(g) : "memory");
}
__device__ __forceinline__ void cp_commit() { asm volatile("cp.async.commit_group;" ::: "memory"); }
__device__ __forceinline__ void cp_wait1()  { asm volatile("cp.async.wait_group 1;" ::: "memory"); }

__device__ __forceinline__ int load_idx(const void* buf, long long i) {
    return g_idx_is_i32 ? ((const int*)buf)[i] : (int)((const long long*)buf)[i];
}

// ---------------------------------------------------------------------------
// prepass kernels: dtype detect, counting sort of edges by dst (per relation)
// ---------------------------------------------------------------------------
__global__ void detect_idx_kernel(const void* srcbuf) {
    const long long* p = (const long long*)srcbuf;
    int tid = threadIdx.x;
    int bad = 0;
    #pragma unroll
    for (int i = 0; i < 4; i++) {
        long long v = p[tid * 4 + i];
        if (v < 0 || v >= NN) bad = 1;
    }
    int any = __syncthreads_or(bad);
    if (tid == 0) g_idx_is_i32 = any;
}

__global__ void zero_hist_kernel() {
    int i = blockIdx.x * blockDim.x + threadIdx.x;
    if (i < NBINS) g_off[i] = 0;
}

__global__ void hist_kernel(const void* dstbuf) {
    long long i = (long long)blockIdx.x * blockDim.x + threadIdx.x;
    if (i >= NEDGES) return;
    int rel = (int)(i / EPR);
    int dst = load_idx(dstbuf, i);
    atomicAdd(&g_off[rel * NN + dst], 1);
}

// block-wise exclusive scan (Hillis-Steele), 1024 items/block
__global__ void scan_local_kernel() {
    __shared__ int sh[SCAN_BLK];
    int i = blockIdx.x * SCAN_BLK + threadIdx.x;
    int v = (i < NBINS) ? g_off[i] : 0;
    sh[threadIdx.x] = v;
    __syncthreads();
    #pragma unroll
    for (int o = 1; o < SCAN_BLK; o <<= 1) {
        int t = (threadIdx.x >= o) ? sh[threadIdx.x - o] : 0;
        __syncthreads();
        sh[threadIdx.x] += t;
        __syncthreads();
    }
    if (i < NBINS) g_off[i] = sh[threadIdx.x] - v;   // exclusive
    if (threadIdx.x == SCAN_BLK - 1) g_bsum[blockIdx.x] = sh[threadIdx.x];
}

__global__ void scan_bsum_kernel() {
    __shared__ int sh[SCAN_BLK];
    int v = (threadIdx.x < NSCANBLK) ? g_bsum[threadIdx.x] : 0;
    sh[threadIdx.x] = v;
    __syncthreads();
    #pragma unroll
    for (int o = 1; o < SCAN_BLK; o <<= 1) {
        int t = (threadIdx.x >= o) ? sh[threadIdx.x - o] : 0;
        __syncthreads();
        sh[threadIdx.x] += t;
        __syncthreads();
    }
    if (threadIdx.x < NSCANBLK) g_bsum[threadIdx.x] = sh[threadIdx.x] - v;  // exclusive
}

__global__ void add_bsum_kernel() {
    int i = blockIdx.x * SCAN_BLK + threadIdx.x;
    if (i < NBINS) g_off[i] += g_bsum[blockIdx.x];
}

__global__ void scatter_kernel(const void* srcbuf, const void* dstbuf) {
    long long i = (long long)blockIdx.x * blockDim.x + threadIdx.x;
    if (i >= NEDGES) return;
    int rel = (int)(i / EPR);
    int src = load_idx(srcbuf, i);
    int dst = load_idx(dstbuf, i);
    int pos = atomicAdd(&g_off[rel * NN + dst], 1);   // global edge slot (relation-major)
    g_src32[pos] = src;
    g_dst32[pos] = dst;
}

// ---------------------------------------------------------------------------
// fp16 conversion prepass
// ---------------------------------------------------------------------------
__global__ void x_to_half(const float* __restrict__ x) {
    long long i = (long long)blockIdx.x * blockDim.x + threadIdx.x;
    if (i >= (long long)NN * DIM / 2) return;
    float2 v = ((const float2*)x)[i];
    g_xh[i] = __floats2half2_rn(v.x, v.y);
}

__global__ void wt_half(const float* __restrict__ src, __half* __restrict__ dst) {
    __shared__ float t[32][33];
    const float* S = src + (size_t)blockIdx.z * DIM * DIM;
    __half* D = dst + (size_t)blockIdx.z * DIM * DIM;
    int bx = blockIdx.x * 32, by = blockIdx.y * 32;
    t[threadIdx.y][threadIdx.x] = S[(size_t)(by + threadIdx.y) * DIM + bx + threadIdx.x];
    __syncthreads();
    D[(size_t)(bx + threadIdx.y) * DIM + by + threadIdx.x] =
        __float2half_rn(t[threadIdx.x][threadIdx.y]);
}

// ---------------------------------------------------------------------------
// fp16 double-buffered cp.async GEMM, fp32 accumulate.
// GATHER=true: dst-sorted edges -> C tile staged to smem -> segmented
// reduction over dst runs -> one red.v4 per run per 4 columns.
// GATHER=false: direct store (self loop).
// ---------------------------------------------------------------------------
template<bool GATHER>
__global__ __launch_bounds__(256, 2)
void rgcn_gemm_f16(const __half* __restrict__ XH,
                   const __half* __restrict__ WT,
                   float* __restrict__ out)
{
    extern __shared__ char smem[];
    int* sSrc = (int*)(smem + OFF_SRC);
    int* sDst = (int*)(smem + OFF_DST);

    const int tid = threadIdx.x;
    const int rel = GATHER ? blockIdx.y : 0;
    const long long base = (long long)blockIdx.x * TM;
    const __half* Wr = WT + (size_t)rel * DIM * DIM;

    if (tid < TM) {
        if constexpr (GATHER) {
            long long off = (long long)rel * EPR + base + tid;
            sSrc[tid] = g_src32[off];
            sDst[tid] = g_dst32[off];
        } else {
            long long r = base + tid;
            sSrc[tid] = (r < NN) ? (int)r : 0;
            sDst[tid] = (r < NN) ? (int)r : -1;
        }
    }
    __syncthreads();

    const int warp = tid >> 5;
    const int lane = tid & 31;
    const int wm = warp >> 2;     // 0..1
    const int wn = warp & 3;      // 0..3
    const int g  = lane >> 2;     // 0..7
    const int t4 = lane & 3;      // 0..3

    const int arow = tid >> 2;
    const int ac   = tid & 3;
    const char* aSrc = (const char*)(XH + (size_t)sSrc[arow] * DIM);
    const char* bSrc = (const char*)(Wr + (size_t)tid * DIM);

    uint32_t sb;
    asm("{ .reg .u64 t; cvta.to.shared.u64 t, %1; cvt.u32.u64 %0, t; }" : "=r"(sb) : "l"(smem));

    const uint32_t offA[2] = { sb + OFF_A0, sb + OFF_A1 };
    const uint32_t offB[2] = { sb + OFF_B0, sb + OFF_B1 };

    auto stage = [&](int kc, int buf) {
        cp_async16(offA[buf] + arow * ROWB + ac * 16,       aSrc + kc * 128 + ac * 16);
        cp_async16(offA[buf] + arow * ROWB + (ac + 4) * 16, aSrc + kc * 128 + (ac + 4) * 16);
        #pragma unroll
        for (int i = 0; i < 8; i++)
            cp_async16(offB[buf] + tid * ROWB + i * 16, bSrc + kc * 128 + i * 16);
    };

    float c[2][8][4];
    #pragma unroll
    for (int mi = 0; mi < 2; mi++)
        #pragma unroll
        for (int j = 0; j < 8; j++)
            #pragma unroll
            for (int q = 0; q < 4; q++)
                c[mi][j][q] = 0.f;

    stage(0, 0);
    cp_commit();

    #pragma unroll 1
    for (int kc = 0; kc < NCHUNK; kc++) {
        if (kc + 1 < NCHUNK) stage(kc + 1, (kc + 1) & 1);
        cp_commit();
        cp_wait1();
        __syncthreads();

        const unsigned* Ab = (const unsigned*)(smem + ((kc & 1) ? OFF_A1 : OFF_A0));
        const unsigned* Bb = (const unsigned*)(smem + ((kc & 1) ? OFF_B1 : OFF_B0));

        #pragma unroll
        for (int s = 0; s < 4; s++) {
            unsigned a[2][4], b[8][2];
            #pragma unroll
            for (int mi = 0; mi < 2; mi++) {
                int rb = wm * 32 + mi * 16 + g;
                a[mi][0] = Ab[(size_t)rb       * 36 + s * 8 + t4];
                a[mi][1] = Ab[(size_t)(rb + 8) * 36 + s * 8 + t4];
                a[mi][2] = Ab[(size_t)rb       * 36 + s * 8 + t4 + 4];
                a[mi][3] = Ab[(size_t)(rb + 8) * 36 + s * 8 + t4 + 4];
            }
            #pragma unroll
            for (int j = 0; j < 8; j++) {
                int n = wn * 64 + j * 8 + g;
                b[j][0] = Bb[(size_t)n * 36 + s * 8 + t4];
                b[j][1] = Bb[(size_t)n * 36 + s * 8 + t4 + 4];
            }
            #pragma unroll
            for (int mi = 0; mi < 2; mi++)
                #pragma unroll
                for (int j = 0; j < 8; j++)
                    mma_f16(c[mi][j], a[mi], b[j]);
        }
        __syncthreads();
    }

    // ---- epilogue ----
    if constexpr (GATHER) {
        // 1) stage C tile to smem (reuse staging area; mainloop done per barrier above)
        float* Cs = (float*)smem;   // [TM][CS_STRIDE]
        #pragma unroll
        for (int mi = 0; mi < 2; mi++) {
            #pragma unroll
            for (int half = 0; half < 2; half++) {
                int r = wm * 32 + mi * 16 + half * 8 + g;
                float* rowp = Cs + (size_t)r * CS_STRIDE + wn * 64;
                #pragma unroll
                for (int j = 0; j < 8; j++) {
                    int col = j * 8 + t4 * 2;
                    *reinterpret_cast<float2*>(rowp + col) =
                        make_float2(c[mi][j][half * 2 + 0], c[mi][j][half * 2 + 1]);
                }
            }
        }
        __syncthreads();

        // 2) segmented reduction: 4 row-segments x 64 col-owners (4 cols each).
        // Edges sorted by dst -> runs of equal dst are contiguous rows.
        const int seg   = tid >> 6;        // 0..3 -> rows [seg*16, seg*16+16)
        const int owner = tid & 63;        // 0..63 -> cols [owner*4, owner*4+4)
        const int col   = owner * 4;
        const int r0    = seg * 16;

        float4 acc = make_float4(0.f, 0.f, 0.f, 0.f);
        int cur = sDst[r0];
        #pragma unroll 4
        for (int r = r0; r < r0 + 16; r++) {
            int d = sDst[r];
            if (d != cur) {
                red_v4(out + (size_t)cur * DIM + col, acc.x, acc.y, acc.z, acc.w);
                acc = make_float4(0.f, 0.f, 0.f, 0.f);
                cur = d;
            }
            float4 v = *reinterpret_cast<const float4*>(Cs + (size_t)r * CS_STRIDE + col);
            acc.x += v.x; acc.y += v.y; acc.z += v.z; acc.w += v.w;
        }
        red_v4(out + (size_t)cur * DIM + col, acc.x, acc.y, acc.z, acc.w);
    } else {
        #pragma unroll
        for (int mi = 0; mi < 2; mi++) {
            #pragma unroll
            for (int half = 0; half < 2; half++) {
                int r = wm * 32 + mi * 16 + half * 8 + g;
                int drow = sDst[r];
                if (drow < 0) continue;
                float* orow = out + (size_t)drow * DIM + wn * 64;
                #pragma unroll
                for (int j = 0; j < 8; j++) {
                    int col = j * 8 + t4 * 2;
                    *reinterpret_cast<float2*>(orow + col) =
                        make_float2(c[mi][j][half * 2 + 0], c[mi][j][half * 2 + 1]);
                }
            }
        }
    }
}

// ---------------------------------------------------------------------------
// LayerNorm over last dim (256). One warp per row.
// ---------------------------------------------------------------------------
__global__ void ln_kernel(float* __restrict__ out,
                          const float* __restrict__ gamma,
                          const float* __restrict__ beta)
{
    int row = blockIdx.x * 8 + (threadIdx.x >> 5);
    if (row >= NN) return;
    int lane = threadIdx.x & 31;
    float* p = out + (size_t)row * DIM;

    float4 v0 = *reinterpret_cast<const float4*>(p + lane * 4);
    float4 v1 = *reinterpret_cast<const float4*>(p + 128 + lane * 4);

    float s  = v0.x + v0.y + v0.z + v0.w + v1.x + v1.y + v1.z + v1.w;
    float sq = fmaf(v0.x, v0.x, fmaf(v0.y, v0.y, fmaf(v0.z, v0.z, v0.w * v0.w)))
             + fmaf(v1.x, v1.x, fmaf(v1.y, v1.y, fmaf(v1.z, v1.z, v1.w * v1.w)));

    #pragma unroll
    for (int o = 16; o; o >>= 1) {
        s  += __shfl_xor_sync(0xffffffffu, s,  o);
        sq += __shfl_xor_sync(0xffffffffu, sq, o);
    }

    float mean = s * (1.f / 256.f);
    float var  = sq * (1.f / 256.f) - mean * mean;
    float rs   = rsqrtf(var + 1e-5f);

    float4 g0 = *reinterpret_cast<const float4*>(gamma + lane * 4);
    float4 g1 = *reinterpret_cast<const float4*>(gamma + 128 + lane * 4);
    float4 b0 = *reinterpret_cast<const float4*>(beta + lane * 4);
    float4 b1 = *reinterpret_cast<const float4*>(beta + 128 + lane * 4);

    v0.x = (v0.x - mean) * rs * g0.x + b0.x;
    v0.y = (v0.y - mean) * rs * g0.y + b0.y;
    v0.z = (v0.z - mean) * rs * g0.z + b0.z;
    v0.w = (v0.w - mean) * rs * g0.w + b0.w;
    v1.x = (v1.x - mean) * rs * g1.x + b1.x;
    v1.y = (v1.y - mean) * rs * g1.y + b1.y;
    v1.z = (v1.z - mean) * rs * g1.z + b1.z;
    v1.w = (v1.w - mean) * rs * g1.w + b1.w;

    *reinterpret_cast<float4*>(p + lane * 4)       = v0;
    *reinterpret_cast<float4*>(p + 128 + lane * 4) = v1;
}

extern "C" void kernel_launch(void* const* d_in, const int* in_sizes, int n_in,
                              void* d_out, int out_size)
{
    const float* x     = (const float*)d_in[0];
    const void*  srcb  = d_in[1];
    const void*  dstb  = d_in[2];
    const float* Wself = (const float*)d_in[3];
    const float* Wrel  = (const float*)d_in[4];
    const float* gamma = (const float*)d_in[5];
    const float* beta  = (const float*)d_in[6];
    float* out = (float*)d_out;

    void *pXh = nullptr, *pWrelT = nullptr, *pWselfT = nullptr;
    cudaGetSymbolAddress(&pXh, g_xh);
    cudaGetSymbolAddress(&pWrelT, g_WrelT);
    cudaGetSymbolAddress(&pWselfT, g_WselfT);

    cudaFuncSetAttribute(rgcn_gemm_f16<false>,
                         cudaFuncAttributeMaxDynamicSharedMemorySize, SMEM_TOTAL);
    cudaFuncSetAttribute(rgcn_gemm_f16<true>,
                         cudaFuncAttributeMaxDynamicSharedMemorySize, SMEM_TOTAL);

    // --- prepass: dtype detect + counting sort of edges by dst (per relation) ---
    detect_idx_kernel<<<1, 256>>>(srcb);
    zero_hist_kernel<<<(NBINS + 1023) / 1024, 1024>>>();
    hist_kernel<<<(NEDGES + 255) / 256, 256>>>(dstb);
    scan_local_kernel<<<NSCANBLK, SCAN_BLK>>>();
    scan_bsum_kernel<<<1, SCAN_BLK>>>();
    add_bsum_kernel<<<NSCANBLK, SCAN_BLK>>>();
    scatter_kernel<<<(NEDGES + 255) / 256, 256>>>(srcb, dstb);

    // --- prepass: fp16 conversions ---
    {
        long long nh2 = (long long)NN * DIM / 2;
        x_to_half<<<(int)((nh2 + 255) / 256), 256>>>(x);
        wt_half<<<dim3(8, 8, NRELS), dim3(32, 32)>>>(Wrel, (__half*)pWrelT);
        wt_half<<<dim3(8, 8, 1), dim3(32, 32)>>>(Wself, (__half*)pWselfT);
    }

    // 1) self loop: out = x @ W_self (direct store initializes out)
    rgcn_gemm_f16<false><<<(NN + TM - 1) / TM, 256, SMEM_TOTAL>>>(
        (const __half*)pXh, (const __half*)pWselfT, out);

    // 2) fused gather -> fp16 GEMM -> segmented-reduced red.v4 scatter
    rgcn_gemm_f16<true><<<dim3(EPR / TM, NRELS), 256, SMEM_TOTAL>>>(
        (const __half*)pXh, (const __half*)pWrelT, out);

    // 3) LayerNorm
    ln_kernel<<<(NN + 7) / 8, 256>>>(out, gamma, beta);
}